// round 1
// baseline (speedup 1.0000x reference)
#include <cuda_runtime.h>

typedef unsigned long long ull;

#define N_CAND 65536
#define HID 1024
#define K1 576        // 512 gathered + 64 cand feats (global-pool folded into bias)
#define C_CH 256
#define HW 361

// ---------------- scratch (static device allocations; no cudaMalloc) ----------------
__device__ float g_pft[HW * C_CH];                 // policy map transposed to [pos][ch]
__device__ float g_gp[C_CH];                       // global pool
__device__ float g_b1eff[HID];                     // b1 + gp @ W1[512:768]
__device__ float g_W1eff[K1 * HID];                // rows [0:512) + [768:832) of W1
__device__ float g_A[(size_t)N_CAND * K1];         // gathered input features
__device__ float g_h1[(size_t)N_CAND * HID];       // layer-1 activations
__device__ float g_part[8 * N_CAND];               // per-N-tile partial scores

// ---------------- packed f32x2 helpers ----------------
__device__ __forceinline__ ull pack2(float lo, float hi) {
    ull r; asm("mov.b64 %0, {%1, %2};" : "=l"(r) : "f"(lo), "f"(hi)); return r;
}
__device__ __forceinline__ float2 unpack2(ull v) {
    float2 r; asm("mov.b64 {%0, %1}, %2;" : "=f"(r.x), "=f"(r.y) : "l"(v)); return r;
}
__device__ __forceinline__ void ffma2(ull &d, ull a, ull b) {
    asm("fma.rn.f32x2 %0, %1, %2, %0;" : "+l"(d) : "l"(a), "l"(b));
}

// ---------------- small prep kernels ----------------
__global__ void k_transpose(const float* __restrict__ pf) {
    int idx = blockIdx.x * 256 + threadIdx.x;
    if (idx < C_CH * HW) {
        int ch = idx / HW, pos = idx % HW;
        g_pft[pos * C_CH + ch] = pf[idx];
    }
}

__global__ void k_pool() {
    int ch = threadIdx.x;          // 256 threads
    float s = 0.f;
    for (int p = 0; p < HW; p++) s += g_pft[p * C_CH + ch];
    g_gp[ch] = s / 361.0f;
}

__global__ void k_b1eff(const float* __restrict__ W1, const float* __restrict__ b1) {
    int j = blockIdx.x * 256 + threadIdx.x;   // 1024 total
    float s = b1[j];
    for (int c = 0; c < C_CH; c++)
        s += g_gp[c] * W1[(size_t)(512 + c) * HID + j];
    g_b1eff[j] = s;
}

__global__ void k_w1eff(const float* __restrict__ W1) {
    int p = blockIdx.x * 256 + threadIdx.x;   // 576*256 float4s
    int row = p >> 8, c4 = p & 255;
    int srcRow = (row < 512) ? row : row + 256;   // rows 512..575 <- W1 rows 768..831
    ((float4*)g_W1eff)[p] = ((const float4*)W1)[(size_t)srcRow * 256 + c4];
}

// one warp per candidate: decode indices, gather go/to features + cand feats
__global__ void k_build(const float* __restrict__ cand) {
    int gwid = (blockIdx.x * blockDim.x + threadIdx.x) >> 5;
    int lane = threadIdx.x & 31;
    const float* cf = cand + (size_t)gwid * 64;
    float f5 = cf[5], f6 = cf[6], f7 = cf[7], f8 = cf[8];
    int gr = min(max((int)(f5 * 18.0f), 0), 18);
    int gc = min(max((int)(f6 * 18.0f), 0), 18);
    int tr = min(max((int)(f7 * 18.0f), 0), 18);
    int tc = min(max((int)(f8 * 18.0f), 0), 18);
    const float4* go4 = (const float4*)(g_pft + (gr * 19 + gc) * C_CH);
    const float4* to4 = (const float4*)(g_pft + (tr * 19 + tc) * C_CH);
    const float4* cf4 = (const float4*)cf;
    float4* out4 = (float4*)(g_A + (size_t)gwid * K1);
    #pragma unroll
    for (int j = lane; j < 144; j += 32) {      // 576/4
        float4 v = (j < 64) ? go4[j] : ((j < 128) ? to4[j - 64] : cf4[j - 128]);
        out4[j] = v;
    }
}

// ---------------- fused SGEMM (128x128x16 tile, 8x8 thread tile, packed f32x2) ----------------
// MODE 0: g_h1 = relu(g_A @ g_W1eff + g_b1eff)           (K = 576)
// MODE 1: g_part[ntile] = sum_j relu(g_h1 @ W2 + b2)*W3  (K = 1024)
template<int MODE>
__global__ __launch_bounds__(256, 2)
void k_gemm(const float* __restrict__ Bext, const float* __restrict__ bias_ext,
            const float* __restrict__ w3)
{
    const float* A    = (MODE == 0) ? g_A     : g_h1;
    const float* B    = (MODE == 0) ? g_W1eff : Bext;
    const float* bias = (MODE == 0) ? g_b1eff : bias_ext;
    const int K       = (MODE == 0) ? K1 : HID;

    __shared__ float As[128][16];
    __shared__ float Bs[16][128];

    const int tid = threadIdx.x;
    const int tx = tid & 15, ty = tid >> 4;
    const int nBase = blockIdx.x * 128;
    const int mBase = blockIdx.y * 128;

    const int ra0 = tid >> 2, qa = (tid & 3) * 4;   // A loader: rows ra0, ra0+64
    const int rb0 = tid >> 5, cb = (tid & 31) * 4;  // B loader: rows rb0, rb0+8

    ull acc[8][4];
    #pragma unroll
    for (int i = 0; i < 8; i++)
        #pragma unroll
        for (int j = 0; j < 4; j++) acc[i][j] = 0ull;

    for (int k0 = 0; k0 < K; k0 += 16) {
        float4 va0 = *(const float4*)&A[(size_t)(mBase + ra0) * K + k0 + qa];
        float4 va1 = *(const float4*)&A[(size_t)(mBase + ra0 + 64) * K + k0 + qa];
        float4 vb0 = *(const float4*)&B[(size_t)(k0 + rb0) * HID + nBase + cb];
        float4 vb1 = *(const float4*)&B[(size_t)(k0 + rb0 + 8) * HID + nBase + cb];
        __syncthreads();
        *(float4*)&As[ra0][qa]      = va0;
        *(float4*)&As[ra0 + 64][qa] = va1;
        *(float4*)&Bs[rb0][cb]      = vb0;
        *(float4*)&Bs[rb0 + 8][cb]  = vb1;
        __syncthreads();

        #pragma unroll
        for (int kk4 = 0; kk4 < 4; kk4++) {
            float a[8][4];
            #pragma unroll
            for (int i = 0; i < 4; i++) {
                *(float4*)a[i]     = *(const float4*)&As[ty * 4 + i][kk4 * 4];
                *(float4*)a[4 + i] = *(const float4*)&As[64 + ty * 4 + i][kk4 * 4];
            }
            #pragma unroll
            for (int dk = 0; dk < 4; dk++) {
                const int k = kk4 * 4 + dk;
                ull b0 = *(const ull*)&Bs[k][tx * 4];
                ull b1 = *(const ull*)&Bs[k][tx * 4 + 2];
                ull b2v = *(const ull*)&Bs[k][64 + tx * 4];
                ull b3v = *(const ull*)&Bs[k][64 + tx * 4 + 2];
                #pragma unroll
                for (int i = 0; i < 8; i++) {
                    ull ap = pack2(a[i][dk], a[i][dk]);
                    ffma2(acc[i][0], ap, b0);
                    ffma2(acc[i][1], ap, b1);
                    ffma2(acc[i][2], ap, b2v);
                    ffma2(acc[i][3], ap, b3v);
                }
            }
        }
    }

    const float* bi = bias + nBase;
    float4 bA = *(const float4*)&bi[tx * 4];
    float4 bB = *(const float4*)&bi[64 + tx * 4];

    if (MODE == 0) {
        #pragma unroll
        for (int i = 0; i < 8; i++) {
            int row = mBase + ((i < 4) ? ty * 4 + i : 64 + ty * 4 + (i - 4));
            float2 p0 = unpack2(acc[i][0]), p1 = unpack2(acc[i][1]);
            float2 p2 = unpack2(acc[i][2]), p3 = unpack2(acc[i][3]);
            float4 v0 = make_float4(fmaxf(p0.x + bA.x, 0.f), fmaxf(p0.y + bA.y, 0.f),
                                    fmaxf(p1.x + bA.z, 0.f), fmaxf(p1.y + bA.w, 0.f));
            float4 v1 = make_float4(fmaxf(p2.x + bB.x, 0.f), fmaxf(p2.y + bB.y, 0.f),
                                    fmaxf(p3.x + bB.z, 0.f), fmaxf(p3.y + bB.w, 0.f));
            *(float4*)&g_h1[(size_t)row * HID + nBase + tx * 4]      = v0;
            *(float4*)&g_h1[(size_t)row * HID + nBase + 64 + tx * 4] = v1;
        }
    } else {
        float4 wA = *(const float4*)&w3[nBase + tx * 4];
        float4 wB = *(const float4*)&w3[nBase + 64 + tx * 4];
        #pragma unroll
        for (int i = 0; i < 8; i++) {
            float2 p0 = unpack2(acc[i][0]), p1 = unpack2(acc[i][1]);
            float2 p2 = unpack2(acc[i][2]), p3 = unpack2(acc[i][3]);
            float s = fmaxf(p0.x + bA.x, 0.f) * wA.x + fmaxf(p0.y + bA.y, 0.f) * wA.y
                    + fmaxf(p1.x + bA.z, 0.f) * wA.z + fmaxf(p1.y + bA.w, 0.f) * wA.w
                    + fmaxf(p2.x + bB.x, 0.f) * wB.x + fmaxf(p2.y + bB.y, 0.f) * wB.y
                    + fmaxf(p3.x + bB.z, 0.f) * wB.z + fmaxf(p3.y + bB.w, 0.f) * wB.w;
            #pragma unroll
            for (int m = 1; m < 16; m <<= 1)
                s += __shfl_xor_sync(0xffffffffu, s, m);
            if (tx == 0) {
                int row = mBase + ((i < 4) ? ty * 4 + i : 64 + ty * 4 + (i - 4));
                g_part[blockIdx.x * N_CAND + row] = s;
            }
        }
    }
}

__global__ void k_reduce(const float* __restrict__ b3, float* __restrict__ out) {
    int n = blockIdx.x * 256 + threadIdx.x;
    float s = b3[0];
    #pragma unroll
    for (int t = 0; t < 8; t++) s += g_part[t * N_CAND + n];
    out[n] = s;
}

// ---------------- launch ----------------
extern "C" void kernel_launch(void* const* d_in, const int* in_sizes, int n_in,
                              void* d_out, int out_size) {
    const float* pf   = (const float*)d_in[0];  // policy_feat_map 256*19*19
    const float* cand = (const float*)d_in[1];  // cand_feats 65536*64
    const float* W1   = (const float*)d_in[2];  // 832*1024
    const float* b1   = (const float*)d_in[3];  // 1024
    const float* W2   = (const float*)d_in[4];  // 1024*1024
    const float* b2   = (const float*)d_in[5];  // 1024
    const float* W3   = (const float*)d_in[6];  // 1024
    const float* b3   = (const float*)d_in[7];  // 1
    float* out = (float*)d_out;

    k_transpose<<<(C_CH * HW + 255) / 256, 256>>>(pf);
    k_pool<<<1, 256>>>();
    k_b1eff<<<4, 256>>>(W1, b1);
    k_w1eff<<<576, 256>>>(W1);
    k_build<<<N_CAND / 8, 256>>>(cand);

    dim3 g(HID / 128, N_CAND / 128);   // (8, 512)
    k_gemm<0><<<g, 256>>>(nullptr, nullptr, nullptr);
    k_gemm<1><<<g, 256>>>(W2, b2, W3);
    k_reduce<<<N_CAND / 256, 256>>>(b3, out);
}

// round 4
// speedup vs baseline: 2.1928x; 2.1928x over previous
#include <cuda_runtime.h>
#include <cuda_bf16.h>
#include <cstdint>

#define N_CAND 65536
#define HID 1024
#define C_CH 256
#define HW 361

// ---------------- scratch ----------------
__device__ float g_pft[HW * C_CH];
__device__ float g_gp[C_CH];
__device__ float g_b1eff[HID];
__device__ float g_P[2 * HW * HID];          // [go/to][pos][1024] fp32
__device__ int   g_go[N_CAND], g_to[N_CAND];
__device__ __nv_bfloat16 g_chi[N_CAND * 64], g_clo[N_CAND * 64];
__device__ __nv_bfloat16 g_Wchi[HID * 64],  g_Wclo[HID * 64];        // W1c^T [n][k]
__device__ __nv_bfloat16 g_Wt2hi[HID * HID], g_Wt2lo[HID * HID];     // W2^T  [n][k]
__device__ __nv_bfloat16 g_h1hi[(size_t)N_CAND * HID], g_h1lo[(size_t)N_CAND * HID];
__device__ float g_part[8 * N_CAND];

// ---------------- helpers ----------------
__device__ __forceinline__ uint32_t smem_u32(const void* p) {
    uint32_t a;
    asm("{ .reg .u64 t; cvta.to.shared.u64 t, %1; cvt.u32.u64 %0, t; }" : "=r"(a) : "l"(p));
    return a;
}
__device__ __forceinline__ void cp16(uint32_t dst, const void* src) {
    asm volatile("cp.async.cg.shared.global [%0], [%1], 16;" :: "r"(dst), "l"(src));
}
__device__ __forceinline__ void cp_commit() { asm volatile("cp.async.commit_group;" ::: "memory"); }
template<int N> __device__ __forceinline__ void cp_wait() {
    asm volatile("cp.async.wait_group %0;" :: "n"(N) : "memory");
}
__device__ __forceinline__ void ldsm4(uint32_t* r, uint32_t a) {
    asm volatile("ldmatrix.sync.aligned.m8n8.x4.shared.b16 {%0,%1,%2,%3}, [%4];"
                 : "=r"(r[0]), "=r"(r[1]), "=r"(r[2]), "=r"(r[3]) : "r"(a));
}
__device__ __forceinline__ void ldsm2(uint32_t* r, uint32_t a) {
    asm volatile("ldmatrix.sync.aligned.m8n8.x2.shared.b16 {%0,%1}, [%2];"
                 : "=r"(r[0]), "=r"(r[1]) : "r"(a));
}
__device__ __forceinline__ void mma16816(float* c, const uint32_t* a, const uint32_t* b) {
    asm volatile("mma.sync.aligned.m16n8k16.row.col.f32.bf16.bf16.f32 "
                 "{%0,%1,%2,%3}, {%4,%5,%6,%7}, {%8,%9}, {%0,%1,%2,%3};"
                 : "+f"(c[0]), "+f"(c[1]), "+f"(c[2]), "+f"(c[3])
                 : "r"(a[0]), "r"(a[1]), "r"(a[2]), "r"(a[3]), "r"(b[0]), "r"(b[1]));
}
__device__ __forceinline__ void split_bf16(float v, __nv_bfloat16& h, __nv_bfloat16& l) {
    h = __float2bfloat16(v);
    l = __float2bfloat16(v - __bfloat162float(h));
}
__device__ __forceinline__ uint32_t pack2bf(__nv_bfloat16 a, __nv_bfloat16 b) {
    return ((uint32_t)__bfloat16_as_ushort(b) << 16) | __bfloat16_as_ushort(a);
}

// ---------------- prep kernels ----------------
__global__ void k_transpose(const float* __restrict__ pf) {
    int idx = blockIdx.x * 256 + threadIdx.x;
    int ch = idx / HW, pos = idx % HW;
    g_pft[pos * C_CH + ch] = pf[idx];
}

__global__ void k_pool() {
    int ch = threadIdx.x;
    float s = 0.f;
    for (int p = 0; p < HW; p++) s += g_pft[p * C_CH + ch];
    g_gp[ch] = s / 361.0f;
}

__global__ void k_b1eff(const float* __restrict__ W1, const float* __restrict__ b1) {
    int j = blockIdx.x * 256 + threadIdx.x;
    float s = b1[j];
    for (int c = 0; c < C_CH; c++) s += g_gp[c] * W1[(size_t)(512 + c) * HID + j];
    g_b1eff[j] = s;
}

// P tables: P[gy][pos][n] = sum_k pft[pos][k] * W1[gy*256 + k][n]   (fp32)
__global__ void k_ptab(const float* __restrict__ W1) {
    int gy = blockIdx.y;
    int p0 = blockIdx.x * 8;
    __shared__ float fs[8][C_CH];
    int tid = threadIdx.x;
    #pragma unroll
    for (int r = 0; r < 8; r++)
        fs[r][tid] = (p0 + r < HW) ? g_pft[(p0 + r) * C_CH + tid] : 0.f;
    __syncthreads();
    int n0 = tid * 4;
    float4 acc[8];
    #pragma unroll
    for (int r = 0; r < 8; r++) acc[r] = make_float4(0.f, 0.f, 0.f, 0.f);
    const float* Wb = W1 + (size_t)gy * C_CH * HID;
    for (int k = 0; k < C_CH; k++) {
        float4 w = *(const float4*)&Wb[(size_t)k * HID + n0];
        #pragma unroll
        for (int r = 0; r < 8; r++) {
            float f = fs[r][k];
            acc[r].x += f * w.x; acc[r].y += f * w.y;
            acc[r].z += f * w.z; acc[r].w += f * w.w;
        }
    }
    #pragma unroll
    for (int r = 0; r < 8; r++)
        if (p0 + r < HW)
            *(float4*)&g_P[((size_t)gy * HW + p0 + r) * HID + n0] = acc[r];
}

__global__ void k_idx(const float* __restrict__ cand) {
    int i = blockIdx.x * 256 + threadIdx.x;
    const float* cf = cand + (size_t)i * 64;
    int gr = min(max((int)(cf[5] * 18.0f), 0), 18);
    int gc = min(max((int)(cf[6] * 18.0f), 0), 18);
    int tr = min(max((int)(cf[7] * 18.0f), 0), 18);
    int tc = min(max((int)(cf[8] * 18.0f), 0), 18);
    g_go[i] = gr * 19 + gc;
    g_to[i] = tr * 19 + tc;
}

__global__ void k_candsplit(const float* __restrict__ cand) {
    int idx = blockIdx.x * 256 + threadIdx.x;   // over N_CAND*16 float4s
    float4 v = ((const float4*)cand)[idx];
    __nv_bfloat16 h0, h1, h2, h3, l0, l1, l2, l3;
    split_bf16(v.x, h0, l0); split_bf16(v.y, h1, l1);
    split_bf16(v.z, h2, l2); split_bf16(v.w, h3, l3);
    ((uint2*)g_chi)[idx] = make_uint2(pack2bf(h0, h1), pack2bf(h2, h3));
    ((uint2*)g_clo)[idx] = make_uint2(pack2bf(l0, l1), pack2bf(l2, l3));
}

__global__ void k_wc(const float* __restrict__ W1) {
    int idx = blockIdx.x * 256 + threadIdx.x;   // n*64 + k
    int n = idx >> 6, k = idx & 63;
    __nv_bfloat16 h, l;
    split_bf16(W1[(size_t)(768 + k) * HID + n], h, l);
    g_Wchi[idx] = h; g_Wclo[idx] = l;
}

__global__ void k_wt2(const float* __restrict__ W2) {
    int idx = blockIdx.x * 256 + threadIdx.x;   // n*1024 + k
    int n = idx >> 10, k = idx & 1023;
    __nv_bfloat16 h, l;
    split_bf16(W2[(size_t)k * HID + n], h, l);
    g_Wt2hi[idx] = h; g_Wt2lo[idx] = l;
}

// ---------------- mma.sync GEMM: CTA 128x128, 8 warps (2m x 4n), warp 64x32 ----------------
// smem stage: Ahi/Alo/Bhi/Blo each 128 rows x 32 bf16, padded to 40 elems (80B) per row
#define ROWB 80
#define OA_HI 0
#define OA_LO 10240
#define OB_HI 20480
#define OB_LO 30720
#define SSTRIDE 40960
#define SMEM_BYTES (3 * SSTRIDE)

template<int MODE, int K, int NC>
__global__ __launch_bounds__(256, 1)
void k_mma(const float* __restrict__ b2, const float* __restrict__ w3) {
    extern __shared__ char smem[];
    const uint32_t sb = smem_u32(smem);
    const int tid = threadIdx.x;
    const int lane = tid & 31, wid = tid >> 5;
    const int wm = wid >> 2, wn = wid & 3;
    const int mBase = blockIdx.y * 128;
    const int nBase = blockIdx.x * 128;

    const __nv_bfloat16* Ahi = (MODE == 0) ? g_chi : g_h1hi;
    const __nv_bfloat16* Alo = (MODE == 0) ? g_clo : g_h1lo;
    const __nv_bfloat16* Bhi = (MODE == 0) ? g_Wchi : g_Wt2hi;
    const __nv_bfloat16* Blo = (MODE == 0) ? g_Wclo : g_Wt2lo;

    const int lrow = tid >> 1;
    const int lc = (tid & 1) * 2;
    const __nv_bfloat16* aHiP = Ahi + (size_t)(mBase + lrow) * K + lc * 8;
    const __nv_bfloat16* aLoP = Alo + (size_t)(mBase + lrow) * K + lc * 8;
    const __nv_bfloat16* bHiP = Bhi + (size_t)(nBase + lrow) * K + lc * 8;
    const __nv_bfloat16* bLoP = Blo + (size_t)(nBase + lrow) * K + lc * 8;
    const uint32_t sA = lrow * ROWB + lc * 16;

    auto load_chunk = [&](int chunk, int buf) {
        uint32_t st = sb + buf * SSTRIDE;
        int k0 = chunk * 32;
        cp16(st + OA_HI + sA,      aHiP + k0);
        cp16(st + OA_HI + sA + 16, aHiP + k0 + 8);
        cp16(st + OA_LO + sA,      aLoP + k0);
        cp16(st + OA_LO + sA + 16, aLoP + k0 + 8);
        cp16(st + OB_HI + sA,      bHiP + k0);
        cp16(st + OB_HI + sA + 16, bHiP + k0 + 8);
        cp16(st + OB_LO + sA,      bLoP + k0);
        cp16(st + OB_LO + sA + 16, bLoP + k0 + 8);
        cp_commit();
    };

    const int NPRE = (NC < 3) ? NC : 3;
    for (int s = 0; s < NPRE; s++) load_chunk(s, s);

    float acc[4][4][4];
    #pragma unroll
    for (int i = 0; i < 4; i++)
        #pragma unroll
        for (int j = 0; j < 4; j++)
            #pragma unroll
            for (int q = 0; q < 4; q++) acc[i][j][q] = 0.f;

    const uint32_t aOff = (uint32_t)((wm * 64 + (lane & 15)) * ROWB + (lane >> 4) * 16);
    const uint32_t bOff = (uint32_t)((wn * 32 + (lane & 7)) * ROWB + ((lane >> 3) & 1) * 16);

    int buf = 0;
    for (int c = 0; c < NC; c++) {
        if (NC - 1 - c >= 2) cp_wait<2>();
        else if (NC - 1 - c == 1) cp_wait<1>();
        else cp_wait<0>();
        __syncthreads();

        uint32_t st = sb + buf * SSTRIDE;
        #pragma unroll
        for (int kk = 0; kk < 2; kk++) {
            uint32_t ah[4][4], al[4][4], bh[4][2], bl[4][2];
            #pragma unroll
            for (int i = 0; i < 4; i++) {
                ldsm4(ah[i], st + OA_HI + aOff + i * (16 * ROWB) + kk * 32);
                ldsm4(al[i], st + OA_LO + aOff + i * (16 * ROWB) + kk * 32);
            }
            #pragma unroll
            for (int j = 0; j < 4; j++) {
                ldsm2(bh[j], st + OB_HI + bOff + j * (8 * ROWB) + kk * 32);
                ldsm2(bl[j], st + OB_LO + bOff + j * (8 * ROWB) + kk * 32);
            }
            #pragma unroll
            for (int i = 0; i < 4; i++)
                #pragma unroll
                for (int j = 0; j < 4; j++) {
                    mma16816(acc[i][j], ah[i], bh[j]);
                    mma16816(acc[i][j], ah[i], bl[j]);
                    mma16816(acc[i][j], al[i], bh[j]);
                }
        }
        __syncthreads();
        if (c + 3 < NC) load_chunk(c + 3, buf);
        buf = (buf + 1 == 3) ? 0 : buf + 1;
    }
    __syncthreads();

    if (MODE == 0) {
        // overlay: go/to indices for this CTA's 128 rows
        int* sgo = (int*)smem;
        int* sto = (int*)(smem + 512);
        if (tid < 128) { sgo[tid] = g_go[mBase + tid]; sto[tid] = g_to[mBase + tid]; }
        __syncthreads();
        #pragma unroll
        for (int i = 0; i < 4; i++) {
            #pragma unroll
            for (int rr = 0; rr < 2; rr++) {
                int rl = wm * 64 + i * 16 + rr * 8 + (lane >> 2);
                size_t row = (size_t)(mBase + rl);
                const float* pg = g_P + (size_t)sgo[rl] * HID;
                const float* pt = g_P + (size_t)(HW + sto[rl]) * HID;
                #pragma unroll
                for (int j = 0; j < 4; j++) {
                    int n = nBase + wn * 32 + j * 8 + 2 * (lane & 3);
                    float v0 = acc[i][j][rr * 2 + 0] + pg[n] + pt[n] + g_b1eff[n];
                    float v1 = acc[i][j][rr * 2 + 1] + pg[n + 1] + pt[n + 1] + g_b1eff[n + 1];
                    v0 = fmaxf(v0, 0.f); v1 = fmaxf(v1, 0.f);
                    __nv_bfloat16 h0, h1, l0, l1;
                    split_bf16(v0, h0, l0); split_bf16(v1, h1, l1);
                    *(uint32_t*)&g_h1hi[row * HID + n] = pack2bf(h0, h1);
                    *(uint32_t*)&g_h1lo[row * HID + n] = pack2bf(l0, l1);
                }
            }
        }
    } else {
        float* red = (float*)smem;   // [4][128]
        #pragma unroll
        for (int i = 0; i < 4; i++) {
            float s0 = 0.f, s1 = 0.f;
            #pragma unroll
            for (int j = 0; j < 4; j++) {
                int n = nBase + wn * 32 + j * 8 + 2 * (lane & 3);
                float bb0 = b2[n], bb1 = b2[n + 1];
                float w0 = w3[n], w1 = w3[n + 1];
                s0 += fmaxf(acc[i][j][0] + bb0, 0.f) * w0 + fmaxf(acc[i][j][1] + bb1, 0.f) * w1;
                s1 += fmaxf(acc[i][j][2] + bb0, 0.f) * w0 + fmaxf(acc[i][j][3] + bb1, 0.f) * w1;
            }
            s0 += __shfl_xor_sync(0xffffffffu, s0, 1);
            s0 += __shfl_xor_sync(0xffffffffu, s0, 2);
            s1 += __shfl_xor_sync(0xffffffffu, s1, 1);
            s1 += __shfl_xor_sync(0xffffffffu, s1, 2);
            if ((lane & 3) == 0) {
                int rl = wm * 64 + i * 16 + (lane >> 2);
                red[wn * 128 + rl] = s0;
                red[wn * 128 + rl + 8] = s1;
            }
        }
        __syncthreads();
        if (tid < 128) {
            float s = red[tid] + red[128 + tid] + red[256 + tid] + red[384 + tid];
            g_part[(size_t)blockIdx.x * N_CAND + mBase + tid] = s;
        }
    }
}

__global__ void k_reduce(const float* __restrict__ b3, float* __restrict__ out) {
    int n = blockIdx.x * 256 + threadIdx.x;
    float s = b3[0];
    #pragma unroll
    for (int t = 0; t < 8; t++) s += g_part[(size_t)t * N_CAND + n];
    out[n] = s;
}

// ---------------- launch ----------------
extern "C" void kernel_launch(void* const* d_in, const int* in_sizes, int n_in,
                              void* d_out, int out_size) {
    const float* pf   = (const float*)d_in[0];
    const float* cand = (const float*)d_in[1];
    const float* W1   = (const float*)d_in[2];
    const float* b1   = (const float*)d_in[3];
    const float* W2   = (const float*)d_in[4];
    const float* b2   = (const float*)d_in[5];
    const float* W3   = (const float*)d_in[6];
    const float* b3   = (const float*)d_in[7];
    float* out = (float*)d_out;

    k_transpose<<<(C_CH * HW) / 256, 256>>>(pf);
    k_pool<<<1, 256>>>();
    k_b1eff<<<HID / 256, 256>>>(W1, b1);
    k_ptab<<<dim3(46, 2), 256>>>(W1);
    k_idx<<<N_CAND / 256, 256>>>(cand);
    k_candsplit<<<(N_CAND * 16) / 256, 256>>>(cand);
    k_wc<<<(HID * 64) / 256, 256>>>(W1);
    k_wt2<<<(HID * HID) / 256, 256>>>(W2);

    cudaFuncSetAttribute(k_mma<0, 64, 2>,    cudaFuncAttributeMaxDynamicSharedMemorySize, SMEM_BYTES);
    cudaFuncSetAttribute(k_mma<1, 1024, 32>, cudaFuncAttributeMaxDynamicSharedMemorySize, SMEM_BYTES);

    dim3 g(HID / 128, N_CAND / 128);   // (8, 512), n fastest for L2 A-reuse
    k_mma<0, 64, 2><<<g, 256, SMEM_BYTES>>>(nullptr, nullptr);
    k_mma<1, 1024, 32><<<g, 256, SMEM_BYTES>>>(b2, W3);
    k_reduce<<<N_CAND / 256, 256>>>(b3, out);
}